// round 16
// baseline (speedup 1.0000x reference)
#include <cuda_runtime.h>
#include <cuda_fp16.h>
#include <cstdint>
#include <cstddef>

// ---------------------------------------------------------------------------
// Problem constants
// ---------------------------------------------------------------------------
#define Bdim  8
#define Fdim  16
#define Pdim  196
#define Ddim  768
#define Hh    12
#define HD    64
#define Ndim  3136              // F*P
#define Mrows 25088             // B*N
#define E3    2304              // 3*D

#define HEAD_ELEMS ((size_t)Bdim * Hh * Ndim * HD)
#define MD_ELEMS   ((size_t)Mrows * Ddim)

// Scratch (__device__ globals; allocation-free rule)
__device__ __half g_q[HEAD_ELEMS];
__device__ __half g_k[HEAD_ELEMS];
__device__ __half g_v[HEAD_ELEMS];

__device__ __half g_x[MD_ELEMS];
__device__ __half g_wqkv[(size_t)E3 * Ddim];
__device__ __half g_wproj[(size_t)Ddim * Ddim];
__device__ __half g_wf[MD_ELEMS];

// ---------------------------------------------------------------------------
// helpers
// ---------------------------------------------------------------------------
__device__ __forceinline__ void cp_async16(uint32_t dst, const void* src) {
    asm volatile("cp.async.cg.shared.global [%0], [%1], 16;"
                 :: "r"(dst), "l"(src) : "memory");
}
#define CP_COMMIT() asm volatile("cp.async.commit_group;" ::: "memory")
template <int N> __device__ __forceinline__ void cp_wait() {
    asm volatile("cp.async.wait_group %0;" :: "n"(N) : "memory");
}
__device__ __forceinline__ uint32_t smem_u32(const void* p) {
    uint32_t a;
    asm("{ .reg .u64 t; cvta.to.shared.u64 t, %1; cvt.u32.u64 %0, t; }"
        : "=r"(a) : "l"(p));
    return a;
}

// fp16 mma
__device__ __forceinline__ void mma16816h(float* d,
                                          uint32_t a0, uint32_t a1, uint32_t a2, uint32_t a3,
                                          uint32_t b0, uint32_t b1) {
    asm volatile(
        "mma.sync.aligned.m16n8k16.row.col.f32.f16.f16.f32 "
        "{%0,%1,%2,%3}, {%4,%5,%6,%7}, {%8,%9}, {%0,%1,%2,%3};"
        : "+f"(d[0]), "+f"(d[1]), "+f"(d[2]), "+f"(d[3])
        : "r"(a0), "r"(a1), "r"(a2), "r"(a3), "r"(b0), "r"(b1));
}

__device__ __forceinline__ void ldsm4(uint32_t& r0, uint32_t& r1,
                                      uint32_t& r2, uint32_t& r3, uint32_t addr) {
    asm volatile("ldmatrix.sync.aligned.m8n8.x4.shared.b16 {%0,%1,%2,%3}, [%4];"
                 : "=r"(r0), "=r"(r1), "=r"(r2), "=r"(r3) : "r"(addr));
}

__device__ __forceinline__ uint32_t pack_h2(float x, float y) {
    __half2 t = __floats2half2_rn(x, y);
    return *(uint32_t*)&t;
}

// ---------------------------------------------------------------------------
// HMMA GEMM (fp16, single-pass, 3-stage pipeline):  C = A[M,768] * B[N,768]^T
// 128x128x32 CTA tile, 256 threads, warp grid 2(M)x4(N), warp tile 64x32.
// LDK=40 (80B rows, conflict-free ldmatrix). cp_wait<1> leaves one chunk in
// flight while computing -> 2 chunks of gmem-latency hiding.
// mode 0: scatter epilogue into fp16 q/k/v head layout; mode 1: C + bias.
// ---------------------------------------------------------------------------
#define BK       32
#define LDK      40
#define TILE_B   (128 * LDK * 2)          // 10240
#define STAGE_B  (2 * TILE_B)             // 20480 (A, B)
#define NSTAGE   3
#define GSMEM    (NSTAGE * STAGE_B)       // 61440
#define OFF_B    TILE_B

__global__ __launch_bounds__(256, 2) void tgemm_k(
    const __half* __restrict__ Am, const __half* __restrict__ Bm,
    const float* __restrict__ bias, float* __restrict__ C, int Nd, int mode,
    __half* __restrict__ Qo, __half* __restrict__ Ko, __half* __restrict__ Vo)
{
    extern __shared__ char smem[];
    const uint32_t sb = smem_u32(smem);

    const int tid  = threadIdx.x;
    const int lane = tid & 31;
    const int wid  = tid >> 5;
    const int wm   = wid & 1;
    const int wn   = wid >> 1;
    const int g    = lane >> 2;
    const int tg   = lane & 3;

    const int bm = blockIdx.y * 128;
    const int bn = blockIdx.x * 128;

    const int a_row = wm * 64 + (lane & 15);
    const int a_kc  = (lane >> 4) * 8;
    const int b_row = wn * 32 + ((lane >> 4) << 3) + (lane & 7);
    const int b_kc  = ((lane >> 3) & 1) * 8;

    auto load_chunk = [&](int k0, int stage) {
        const uint32_t dbase = sb + stage * STAGE_B;
#pragma unroll
        for (int j = 0; j < 4; j++) {
            const int tile = j >> 1;                 // 0:A 1:B
            const int within = tid + (j & 1) * 256;  // 0..511
            const int row = within >> 2;
            const int gr  = within & 3;
            const __half* srcb = (tile == 0) ? Am : Bm;
            const int rowb = (tile == 0) ? bm : bn;
            const void* src = srcb + (size_t)(rowb + row) * Ddim + k0 + gr * 8;
            cp_async16(dbase + (uint32_t)(tile * TILE_B + row * (LDK * 2) + gr * 16), src);
        }
        CP_COMMIT();
    };

    float acc[4][4][4];
#pragma unroll
    for (int i = 0; i < 4; i++)
#pragma unroll
        for (int j = 0; j < 4; j++)
#pragma unroll
            for (int q = 0; q < 4; q++) acc[i][j][q] = 0.f;

    load_chunk(0, 0);
    load_chunk(BK, 1);

    const int NCH = Ddim / BK;   // 24
    for (int c = 0; c < NCH; c++) {
        if (c + 1 < NCH) cp_wait<1>(); else cp_wait<0>();
        __syncthreads();
        if (c + 2 < NCH) load_chunk((c + 2) * BK, (c + 2) % NSTAGE);

        const uint32_t st = sb + (c % NSTAGE) * STAGE_B;

#pragma unroll
        for (int ks = 0; ks < 2; ks++) {
            const int kcA = ks * 16 + a_kc;
            const int kcB = ks * 16 + b_kc;
            uint32_t ah[4][4];
#pragma unroll
            for (int mt = 0; mt < 4; mt++) {
                uint32_t addr = st + (uint32_t)(((a_row + mt * 16) * LDK + kcA) * 2);
                ldsm4(ah[mt][0], ah[mt][1], ah[mt][2], ah[mt][3], addr);
            }
#pragma unroll
            for (int p = 0; p < 2; p++) {
                uint32_t baddr = st + (uint32_t)(((b_row + p * 16) * LDK + kcB) * 2);
                uint32_t bh[2][2];
                ldsm4(bh[0][0], bh[0][1], bh[1][0], bh[1][1], baddr + OFF_B);
#pragma unroll
                for (int q = 0; q < 2; q++) {
                    const int nt = p * 2 + q;
#pragma unroll
                    for (int mt = 0; mt < 4; mt++) {
                        mma16816h(acc[mt][nt], ah[mt][0], ah[mt][1], ah[mt][2], ah[mt][3],
                                  bh[q][0], bh[q][1]);
                    }
                }
            }
        }
    }

    if (mode == 1) {
#pragma unroll
        for (int mt = 0; mt < 4; mt++) {
            int r0 = bm + wm * 64 + mt * 16 + g;
#pragma unroll
            for (int nt = 0; nt < 4; nt++) {
                int c0 = bn + wn * 32 + nt * 8 + tg * 2;
                float b0 = bias[c0], b1 = bias[c0 + 1];
                float2 v0 = make_float2(acc[mt][nt][0] + b0, acc[mt][nt][1] + b1);
                float2 v1 = make_float2(acc[mt][nt][2] + b0, acc[mt][nt][3] + b1);
                *(float2*)(C + (size_t)r0 * Nd + c0) = v0;
                *(float2*)(C + (size_t)(r0 + 8) * Nd + c0) = v1;
            }
        }
    } else {
        // scatter into fp16 q/k/v (B,12,N,64) head layout
#pragma unroll
        for (int nt = 0; nt < 4; nt++) {
            int c0 = bn + wn * 32 + nt * 8 + tg * 2;
            int t = c0 / Ddim;
            int rem = c0 - t * Ddim;
            int h = rem >> 6, d = rem & 63;
            __half* dst = (t == 0) ? Qo : (t == 1) ? Ko : Vo;
#pragma unroll
            for (int mt = 0; mt < 4; mt++) {
                int r0 = bm + wm * 64 + mt * 16 + g;
#pragma unroll
                for (int rr = 0; rr < 2; rr++) {
                    int r = r0 + rr * 8;
                    int b = r / Ndim;
                    int n = r - b * Ndim;
                    size_t off = (((size_t)(b * Hh + h)) * Ndim + n) * HD + d;
                    __half2 hv = __floats2half2_rn(acc[mt][nt][2 * rr], acc[mt][nt][2 * rr + 1]);
                    *(__half2*)(dst + off) = hv;
                }
            }
        }
    }
}

// ---------------------------------------------------------------------------
// fp32 -> fp16
// ---------------------------------------------------------------------------
__global__ void cvt_h(const float* __restrict__ in, __half* __restrict__ out, size_t n)
{
    size_t i = (size_t)blockIdx.x * 256 + threadIdx.x;
    if (i >= n) return;
    out[i] = __float2half(in[i]);
}

// ---------------------------------------------------------------------------
// Fused attention kernel: blocks [0,768) = MMA flash spatial (heads 0..5);
// blocks [768, 768+TEMP_BLKS) = temporal (heads 6..11), 416 thr each.
// ---------------------------------------------------------------------------
#define AT_T    416
#define MPAD    208
#define LDA     72
#define OQ      0
#define OK      (MPAD * LDA * 2)          // 29952
#define OV      (OK + 64 * LDA * 2)       // 39168
#define ATSMEM  (OV + 64 * LDA * 2)       // 48384

#define TEMP_TOT  (Bdim * 6 * Ndim)       // 150528
#define TEMP_BLKS ((TEMP_TOT + AT_T - 1) / AT_T)   // 362

__device__ __forceinline__ void spatial_body(char* smem)
{
    const uint32_t sb = smem_u32(smem);
    __half* Qs = (__half*)(smem + OQ);
    __half* Ks = (__half*)(smem + OK);
    __half* Vt = (__half*)(smem + OV);

    const int grp = blockIdx.x;
    const int b = grp / 96;
    const int h = (grp % 96) / 16;
    const int f = grp % 16;
    const size_t base = (((size_t)(b * Hh + h)) * Ndim + f * Pdim) * HD;

    const int tid  = threadIdx.x;
    const int lane = tid & 31;
    const int wid  = tid >> 5;
    const int gq   = lane >> 2;
    const int tg   = lane & 3;

    // fill Q
    {
        const uint4 z = make_uint4(0, 0, 0, 0);
        for (int idx = tid; idx < MPAD * 8; idx += AT_T) {
            int r = idx >> 3, c8 = (idx & 7) * 8;
            uint4 u = (r < Pdim) ? *(const uint4*)(g_q + base + (size_t)r * HD + c8) : z;
            *(uint4*)(Qs + r * LDA + c8) = u;
        }
    }
    __syncthreads();

    uint32_t qh[4][4];
    {
        const int arow = wid * 16 + (lane & 15);
        const int acol = (lane >> 4) * 8;
#pragma unroll
        for (int kb = 0; kb < 4; kb++) {
            uint32_t addr = sb + (uint32_t)((arow * LDA + kb * 16 + acol) * 2) + OQ;
            ldsm4(qh[kb][0], qh[kb][1], qh[kb][2], qh[kb][3], addr);
        }
    }

    float ofr[8][4];
#pragma unroll
    for (int j = 0; j < 8; j++)
#pragma unroll
        for (int q = 0; q < 4; q++) ofr[j][q] = 0.f;
    float mx0 = -1e30f, mx1 = -1e30f, ls0 = 0.f, ls1 = 0.f;
    const float scale = 0.125f;

    const int brow = ((lane >> 4) << 3) + (lane & 7);
    const int bcol = ((lane >> 3) & 1) * 8;

    for (int ch = 0; ch < 4; ch++) {
        __syncthreads();
        const int kbase = ch * 64;
        {
            const uint4 z = make_uint4(0, 0, 0, 0);
            for (int idx = tid; idx < 64 * 8; idx += AT_T) {
                int r = idx >> 3, c8 = (idx & 7) * 8;
                int key = kbase + r;
                uint4 u = (key < Pdim) ? *(const uint4*)(g_k + base + (size_t)key * HD + c8) : z;
                *(uint4*)(Ks + r * LDA + c8) = u;
            }
        }
        for (int idx = tid; idx < 64 * 8; idx += AT_T) {
            int r = idx >> 3, c8 = (idx & 7) * 8;
            int key = kbase + r;
            if (key < Pdim) {
                uint4 u = *(const uint4*)(g_v + base + (size_t)key * HD + c8);
                const __half* hp = (const __half*)&u;
#pragma unroll
                for (int j = 0; j < 8; j++) Vt[(c8 + j) * LDA + r] = hp[j];
            } else {
                const __half z = __float2half(0.f);
#pragma unroll
                for (int j = 0; j < 8; j++) Vt[(c8 + j) * LDA + r] = z;
            }
        }
        __syncthreads();

        float sfr[8][4];
#pragma unroll
        for (int j = 0; j < 8; j++)
#pragma unroll
            for (int q = 0; q < 4; q++) sfr[j][q] = 0.f;

#pragma unroll
        for (int kb = 0; kb < 4; kb++) {
#pragma unroll
            for (int p = 0; p < 4; p++) {
                uint32_t ka = sb + (uint32_t)(((p * 16 + brow) * LDA + kb * 16 + bcol) * 2) + OK;
                uint32_t bh0, bh1, bh2, bh3;
                ldsm4(bh0, bh1, bh2, bh3, ka);
                mma16816h(sfr[2 * p], qh[kb][0], qh[kb][1], qh[kb][2], qh[kb][3], bh0, bh1);
                mma16816h(sfr[2 * p + 1], qh[kb][0], qh[kb][1], qh[kb][2], qh[kb][3], bh2, bh3);
            }
        }

        const int nvalid = Pdim - kbase;
#pragma unroll
        for (int j = 0; j < 8; j++)
#pragma unroll
            for (int q = 0; q < 4; q++) {
                int key = j * 8 + 2 * tg + (q & 1);
                sfr[j][q] = (key < nvalid) ? sfr[j][q] * scale : -1e30f;
            }

        float rm0 = -1e30f, rm1 = -1e30f;
#pragma unroll
        for (int j = 0; j < 8; j++) {
            rm0 = fmaxf(rm0, fmaxf(sfr[j][0], sfr[j][1]));
            rm1 = fmaxf(rm1, fmaxf(sfr[j][2], sfr[j][3]));
        }
        rm0 = fmaxf(rm0, __shfl_xor_sync(0xFFFFFFFFu, rm0, 1));
        rm0 = fmaxf(rm0, __shfl_xor_sync(0xFFFFFFFFu, rm0, 2));
        rm1 = fmaxf(rm1, __shfl_xor_sync(0xFFFFFFFFu, rm1, 1));
        rm1 = fmaxf(rm1, __shfl_xor_sync(0xFFFFFFFFu, rm1, 2));
        float nm0 = fmaxf(mx0, rm0), nm1 = fmaxf(mx1, rm1);
        float c0 = __expf(mx0 - nm0), c1 = __expf(mx1 - nm1);
        mx0 = nm0; mx1 = nm1;
        ls0 *= c0; ls1 *= c1;
#pragma unroll
        for (int j = 0; j < 8; j++) {
            ofr[j][0] *= c0; ofr[j][1] *= c0;
            ofr[j][2] *= c1; ofr[j][3] *= c1;
        }

        float rs0 = 0.f, rs1 = 0.f;
#pragma unroll
        for (int j = 0; j < 8; j++) {
            float p0 = __expf(sfr[j][0] - nm0);
            float p1 = __expf(sfr[j][1] - nm0);
            float p2 = __expf(sfr[j][2] - nm1);
            float p3 = __expf(sfr[j][3] - nm1);
            rs0 += p0 + p1; rs1 += p2 + p3;
            sfr[j][0] = p0; sfr[j][1] = p1; sfr[j][2] = p2; sfr[j][3] = p3;
        }
        rs0 += __shfl_xor_sync(0xFFFFFFFFu, rs0, 1);
        rs0 += __shfl_xor_sync(0xFFFFFFFFu, rs0, 2);
        rs1 += __shfl_xor_sync(0xFFFFFFFFu, rs1, 1);
        rs1 += __shfl_xor_sync(0xFFFFFFFFu, rs1, 2);
        ls0 += rs0; ls1 += rs1;

#pragma unroll
        for (int kb = 0; kb < 4; kb++) {
            uint32_t pah[4], pal[4];
#pragma unroll
            for (int half = 0; half < 2; half++) {
                const int j = 2 * kb + half;
                float p0 = sfr[j][0], p1 = sfr[j][1], p2 = sfr[j][2], p3 = sfr[j][3];
                __half h0 = __float2half(p0);
                __half h1 = __float2half(p1);
                __half h2 = __float2half(p2);
                __half h3 = __float2half(p3);
                pah[2 * half + 0] = pack_h2(__half2float(h0), __half2float(h1));
                pah[2 * half + 1] = pack_h2(__half2float(h2), __half2float(h3));
                pal[2 * half + 0] = pack_h2(p0 - __half2float(h0), p1 - __half2float(h1));
                pal[2 * half + 1] = pack_h2(p2 - __half2float(h2), p3 - __half2float(h3));
            }
#pragma unroll
            for (int p = 0; p < 4; p++) {
                uint32_t va = sb + (uint32_t)(((p * 16 + brow) * LDA + kb * 16 + bcol) * 2) + OV;
                uint32_t vh0, vh1, vh2, vh3;
                ldsm4(vh0, vh1, vh2, vh3, va);
                mma16816h(ofr[2 * p], pah[0], pah[1], pah[2], pah[3], vh0, vh1);
                mma16816h(ofr[2 * p], pal[0], pal[1], pal[2], pal[3], vh0, vh1);
                mma16816h(ofr[2 * p + 1], pah[0], pah[1], pah[2], pah[3], vh2, vh3);
                mma16816h(ofr[2 * p + 1], pal[0], pal[1], pal[2], pal[3], vh2, vh3);
            }
        }
    }

    float inv0 = 1.f / ls0, inv1 = 1.f / ls1;
    const int r0 = wid * 16 + gq;
    const int r1 = r0 + 8;
    if (r0 < Pdim) {
        const size_t ob = ((size_t)b * Ndim + (f * Pdim + r0)) * Ddim + h * HD;
#pragma unroll
        for (int j = 0; j < 8; j++) {
            __half2 hv = __floats2half2_rn(ofr[j][0] * inv0, ofr[j][1] * inv0);
            *(__half2*)(g_wf + ob + j * 8 + 2 * tg) = hv;
        }
    }
    if (r1 < Pdim) {
        const size_t ob = ((size_t)b * Ndim + (f * Pdim + r1)) * Ddim + h * HD;
#pragma unroll
        for (int j = 0; j < 8; j++) {
            __half2 hv = __floats2half2_rn(ofr[j][2] * inv1, ofr[j][3] * inv1);
            *(__half2*)(g_wf + ob + j * 8 + 2 * tg) = hv;
        }
    }
}

__device__ __forceinline__ void temporal_body()
{
    int tid = (blockIdx.x - 768) * AT_T + threadIdx.x;
    if (tid >= TEMP_TOT) return;
    int b = tid / (6 * Ndim);
    int rr = tid - b * (6 * Ndim);
    int h = 6 + rr / Ndim;
    int n = rr % Ndim;
    int n0 = n & ~15;
    size_t row = (((size_t)(b * Hh + h)) * Ndim + n) * HD;
    size_t gb  = (((size_t)(b * Hh + h)) * Ndim + n0) * HD;

    float qr[64];
    {
        const uint4* qp = (const uint4*)(g_q + row);
#pragma unroll
        for (int i = 0; i < 8; i++) {
            uint4 u = qp[i];
            const __half2* hp = (const __half2*)&u;
#pragma unroll
            for (int j = 0; j < 4; j++) {
                float2 t = __half22float2(hp[j]);
                qr[i * 8 + 2 * j] = t.x;
                qr[i * 8 + 2 * j + 1] = t.y;
            }
        }
    }

    float s[16];
    float mx = -1e30f;
#pragma unroll
    for (int f = 0; f < 16; f++) {
        const uint4* kp = (const uint4*)(g_k + gb + (size_t)f * HD);
        float a = 0.f;
#pragma unroll
        for (int i = 0; i < 8; i++) {
            uint4 u = kp[i];
            const __half2* hp = (const __half2*)&u;
#pragma unroll
            for (int j = 0; j < 4; j++) {
                float2 t = __half22float2(hp[j]);
                a = fmaf(qr[i * 8 + 2 * j], t.x, a);
                a = fmaf(qr[i * 8 + 2 * j + 1], t.y, a);
            }
        }
        s[f] = a * 0.125f;
        mx = fmaxf(mx, s[f]);
    }
    float lsum = 0.f;
#pragma unroll
    for (int f = 0; f < 16; f++) { s[f] = __expf(s[f] - mx); lsum += s[f]; }
    float inv = 1.f / lsum;
#pragma unroll
    for (int f = 0; f < 16; f++) s[f] *= inv;

    const size_t obase = ((size_t)b * Ndim + n) * Ddim + h * HD;
#pragma unroll
    for (int ch = 0; ch < 4; ch++) {
        float a16[16];
#pragma unroll
        for (int i = 0; i < 16; i++) a16[i] = 0.f;
#pragma unroll
        for (int f = 0; f < 16; f++) {
            float p = s[f];
            const uint4* vp = (const uint4*)(g_v + gb + (size_t)f * HD + ch * 16);
#pragma unroll
            for (int i = 0; i < 2; i++) {
                uint4 u = vp[i];
                const __half2* hp = (const __half2*)&u;
#pragma unroll
                for (int j = 0; j < 4; j++) {
                    float2 t = __half22float2(hp[j]);
                    a16[i * 8 + 2 * j]     = fmaf(p, t.x, a16[i * 8 + 2 * j]);
                    a16[i * 8 + 2 * j + 1] = fmaf(p, t.y, a16[i * 8 + 2 * j + 1]);
                }
            }
        }
#pragma unroll
        for (int i = 0; i < 8; i++) {
            __half2 hv = __floats2half2_rn(a16[2 * i], a16[2 * i + 1]);
            *(__half2*)(g_wf + obase + ch * 16 + 2 * i) = hv;
        }
    }
}

__global__ __launch_bounds__(AT_T, 1) void attn_fused_k()
{
    extern __shared__ char smem[];
    if (blockIdx.x < 768) spatial_body(smem);
    else                  temporal_body();
}

// ---------------------------------------------------------------------------
// Launch
// ---------------------------------------------------------------------------
extern "C" void kernel_launch(void* const* d_in, const int* in_sizes, int n_in,
                              void* d_out, int out_size)
{
    const float* x      = (const float*)d_in[0];
    const float* w_qkv  = (const float*)d_in[1];
    const float* w_proj = (const float*)d_in[2];
    const float* b_proj = (const float*)d_in[3];
    float* out = (float*)d_out;

    __half *p_q, *p_k, *p_v, *p_x, *p_wqkv, *p_wproj, *p_wf;
    cudaGetSymbolAddress((void**)&p_q, g_q);
    cudaGetSymbolAddress((void**)&p_k, g_k);
    cudaGetSymbolAddress((void**)&p_v, g_v);
    cudaGetSymbolAddress((void**)&p_x, g_x);
    cudaGetSymbolAddress((void**)&p_wqkv, g_wqkv);
    cudaGetSymbolAddress((void**)&p_wproj, g_wproj);
    cudaGetSymbolAddress((void**)&p_wf, g_wf);

    cudaFuncSetAttribute(tgemm_k, cudaFuncAttributeMaxDynamicSharedMemorySize, GSMEM);
    cudaFuncSetAttribute(attn_fused_k, cudaFuncAttributeMaxDynamicSharedMemorySize, ATSMEM);

    // 0) fp16 conversions
    cvt_h<<<(unsigned)((MD_ELEMS + 255) / 256), 256>>>(x, p_x, MD_ELEMS);
    cvt_h<<<(unsigned)(((size_t)E3 * Ddim + 255) / 256), 256>>>(
        w_qkv, p_wqkv, (size_t)E3 * Ddim);
    cvt_h<<<(unsigned)(((size_t)Ddim * Ddim + 255) / 256), 256>>>(
        w_proj, p_wproj, (size_t)Ddim * Ddim);

    // 1) qkv GEMM (1-pass, 3-stage) with fused scatter into fp16 q/k/v
    tgemm_k<<<dim3(E3 / 128, Mrows / 128), 256, GSMEM>>>(
        p_x, p_wqkv, nullptr, nullptr, E3, 0, p_q, p_k, p_v);

    // 2) fused spatial + temporal attention
    attn_fused_k<<<768 + TEMP_BLKS, AT_T, ATSMEM>>>();

    // 3) out = wf @ w_proj^T + b_proj (1-pass, 3-stage)
    tgemm_k<<<dim3(Ddim / 128, Mrows / 128), 256, GSMEM>>>(
        p_wf, p_wproj, b_proj, out, Ddim, 1, nullptr, nullptr, nullptr);
}

// round 17
// speedup vs baseline: 1.0338x; 1.0338x over previous
#include <cuda_runtime.h>
#include <cuda_fp16.h>
#include <cstdint>
#include <cstddef>

// ---------------------------------------------------------------------------
// Problem constants
// ---------------------------------------------------------------------------
#define Bdim  8
#define Fdim  16
#define Pdim  196
#define Ddim  768
#define Hh    12
#define HD    64
#define Ndim  3136              // F*P
#define Mrows 25088             // B*N
#define E3    2304              // 3*D

#define HEAD_ELEMS ((size_t)Bdim * Hh * Ndim * HD)
#define MD_ELEMS   ((size_t)Mrows * Ddim)
#define WQKV_ELEMS ((size_t)E3 * Ddim)
#define WPRJ_ELEMS ((size_t)Ddim * Ddim)

// Scratch (__device__ globals; allocation-free rule)
__device__ __half g_q[HEAD_ELEMS];
__device__ __half g_k[HEAD_ELEMS];
__device__ __half g_v[HEAD_ELEMS];

__device__ __half g_x[MD_ELEMS];
__device__ __half g_wqkv[WQKV_ELEMS];
__device__ __half g_wproj[WPRJ_ELEMS];
__device__ __half g_wf[MD_ELEMS];

// ---------------------------------------------------------------------------
// helpers
// ---------------------------------------------------------------------------
__device__ __forceinline__ void cp_async16(uint32_t dst, const void* src) {
    asm volatile("cp.async.cg.shared.global [%0], [%1], 16;"
                 :: "r"(dst), "l"(src) : "memory");
}
#define CP_COMMIT() asm volatile("cp.async.commit_group;" ::: "memory")
template <int N> __device__ __forceinline__ void cp_wait() {
    asm volatile("cp.async.wait_group %0;" :: "n"(N) : "memory");
}
__device__ __forceinline__ uint32_t smem_u32(const void* p) {
    uint32_t a;
    asm("{ .reg .u64 t; cvta.to.shared.u64 t, %1; cvt.u32.u64 %0, t; }"
        : "=r"(a) : "l"(p));
    return a;
}

// fp16 mma
__device__ __forceinline__ void mma16816h(float* d,
                                          uint32_t a0, uint32_t a1, uint32_t a2, uint32_t a3,
                                          uint32_t b0, uint32_t b1) {
    asm volatile(
        "mma.sync.aligned.m16n8k16.row.col.f32.f16.f16.f32 "
        "{%0,%1,%2,%3}, {%4,%5,%6,%7}, {%8,%9}, {%0,%1,%2,%3};"
        : "+f"(d[0]), "+f"(d[1]), "+f"(d[2]), "+f"(d[3])
        : "r"(a0), "r"(a1), "r"(a2), "r"(a3), "r"(b0), "r"(b1));
}

__device__ __forceinline__ void ldsm4(uint32_t& r0, uint32_t& r1,
                                      uint32_t& r2, uint32_t& r3, uint32_t addr) {
    asm volatile("ldmatrix.sync.aligned.m8n8.x4.shared.b16 {%0,%1,%2,%3}, [%4];"
                 : "=r"(r0), "=r"(r1), "=r"(r2), "=r"(r3) : "r"(addr));
}

__device__ __forceinline__ uint32_t pack_h2(float x, float y) {
    __half2 t = __floats2half2_rn(x, y);
    return *(uint32_t*)&t;
}

// ---------------------------------------------------------------------------
// HMMA GEMM (fp16, single-pass, 2-stage — R14 config):
// C = A[M,768] * B[N,768]^T. 128x128x32 CTA tile, 256 threads,
// warp grid 2(M)x4(N), warp tile 64x32. LDK=40, single sync per chunk.
// mode 0: scatter epilogue into fp16 q/k/v head layout; mode 1: C + bias.
// ---------------------------------------------------------------------------
#define BK       32
#define LDK      40
#define TILE_B   (128 * LDK * 2)          // 10240
#define STAGE_B  (2 * TILE_B)             // 20480 (A, B)
#define GSMEM    (2 * STAGE_B)            // 40960
#define OFF_B    TILE_B

__global__ __launch_bounds__(256, 2) void tgemm_k(
    const __half* __restrict__ Am, const __half* __restrict__ Bm,
    const float* __restrict__ bias, float* __restrict__ C, int Nd, int mode,
    __half* __restrict__ Qo, __half* __restrict__ Ko, __half* __restrict__ Vo)
{
    extern __shared__ char smem[];
    const uint32_t sb = smem_u32(smem);

    const int tid  = threadIdx.x;
    const int lane = tid & 31;
    const int wid  = tid >> 5;
    const int wm   = wid & 1;
    const int wn   = wid >> 1;
    const int g    = lane >> 2;
    const int tg   = lane & 3;

    const int bm = blockIdx.y * 128;
    const int bn = blockIdx.x * 128;

    const int a_row = wm * 64 + (lane & 15);
    const int a_kc  = (lane >> 4) * 8;
    const int b_row = wn * 32 + ((lane >> 4) << 3) + (lane & 7);
    const int b_kc  = ((lane >> 3) & 1) * 8;

    auto load_chunk = [&](int k0, int stage) {
        const uint32_t dbase = sb + stage * STAGE_B;
#pragma unroll
        for (int j = 0; j < 4; j++) {
            const int tile = j >> 1;                 // 0:A 1:B
            const int within = tid + (j & 1) * 256;  // 0..511
            const int row = within >> 2;
            const int gr  = within & 3;
            const __half* srcb = (tile == 0) ? Am : Bm;
            const int rowb = (tile == 0) ? bm : bn;
            const void* src = srcb + (size_t)(rowb + row) * Ddim + k0 + gr * 8;
            cp_async16(dbase + (uint32_t)(tile * TILE_B + row * (LDK * 2) + gr * 16), src);
        }
        CP_COMMIT();
    };

    float acc[4][4][4];
#pragma unroll
    for (int i = 0; i < 4; i++)
#pragma unroll
        for (int j = 0; j < 4; j++)
#pragma unroll
            for (int q = 0; q < 4; q++) acc[i][j][q] = 0.f;

    load_chunk(0, 0);

    const int NCH = Ddim / BK;   // 24
    for (int c = 0; c < NCH; c++) {
        cp_wait<0>();
        __syncthreads();
        if (c + 1 < NCH) load_chunk((c + 1) * BK, (c + 1) & 1);

        const uint32_t st = sb + (c & 1) * STAGE_B;

#pragma unroll
        for (int ks = 0; ks < 2; ks++) {
            const int kcA = ks * 16 + a_kc;
            const int kcB = ks * 16 + b_kc;
            uint32_t ah[4][4];
#pragma unroll
            for (int mt = 0; mt < 4; mt++) {
                uint32_t addr = st + (uint32_t)(((a_row + mt * 16) * LDK + kcA) * 2);
                ldsm4(ah[mt][0], ah[mt][1], ah[mt][2], ah[mt][3], addr);
            }
#pragma unroll
            for (int p = 0; p < 2; p++) {
                uint32_t baddr = st + (uint32_t)(((b_row + p * 16) * LDK + kcB) * 2);
                uint32_t bh[2][2];
                ldsm4(bh[0][0], bh[0][1], bh[1][0], bh[1][1], baddr + OFF_B);
#pragma unroll
                for (int q = 0; q < 2; q++) {
                    const int nt = p * 2 + q;
#pragma unroll
                    for (int mt = 0; mt < 4; mt++) {
                        mma16816h(acc[mt][nt], ah[mt][0], ah[mt][1], ah[mt][2], ah[mt][3],
                                  bh[q][0], bh[q][1]);
                    }
                }
            }
        }
    }

    if (mode == 1) {
#pragma unroll
        for (int mt = 0; mt < 4; mt++) {
            int r0 = bm + wm * 64 + mt * 16 + g;
#pragma unroll
            for (int nt = 0; nt < 4; nt++) {
                int c0 = bn + wn * 32 + nt * 8 + tg * 2;
                float b0 = bias[c0], b1 = bias[c0 + 1];
                float2 v0 = make_float2(acc[mt][nt][0] + b0, acc[mt][nt][1] + b1);
                float2 v1 = make_float2(acc[mt][nt][2] + b0, acc[mt][nt][3] + b1);
                *(float2*)(C + (size_t)r0 * Nd + c0) = v0;
                *(float2*)(C + (size_t)(r0 + 8) * Nd + c0) = v1;
            }
        }
    } else {
        // scatter into fp16 q/k/v (B,12,N,64) head layout
#pragma unroll
        for (int nt = 0; nt < 4; nt++) {
            int c0 = bn + wn * 32 + nt * 8 + tg * 2;
            int t = c0 / Ddim;
            int rem = c0 - t * Ddim;
            int h = rem >> 6, d = rem & 63;
            __half* dst = (t == 0) ? Qo : (t == 1) ? Ko : Vo;
#pragma unroll
            for (int mt = 0; mt < 4; mt++) {
                int r0 = bm + wm * 64 + mt * 16 + g;
#pragma unroll
                for (int rr = 0; rr < 2; rr++) {
                    int r = r0 + rr * 8;
                    int b = r / Ndim;
                    int n = r - b * Ndim;
                    size_t off = (((size_t)(b * Hh + h)) * Ndim + n) * HD + d;
                    __half2 hv = __floats2half2_rn(acc[mt][nt][2 * rr], acc[mt][nt][2 * rr + 1]);
                    *(__half2*)(dst + off) = hv;
                }
            }
        }
    }
}

// ---------------------------------------------------------------------------
// Fused fp32 -> fp16 conversion of x | w_qkv | w_proj in one launch
// ---------------------------------------------------------------------------
__global__ void cvt_all_k(const float* __restrict__ x,
                          const float* __restrict__ wqkv,
                          const float* __restrict__ wproj)
{
    size_t i = (size_t)blockIdx.x * 256 + threadIdx.x;
    const size_t n0 = MD_ELEMS;
    const size_t n1 = n0 + WQKV_ELEMS;
    const size_t n2 = n1 + WPRJ_ELEMS;
    if (i >= n2) return;
    if (i < n0)       g_x[i]          = __float2half(x[i]);
    else if (i < n1)  g_wqkv[i - n0]  = __float2half(wqkv[i - n0]);
    else              g_wproj[i - n1] = __float2half(wproj[i - n1]);
}

// ---------------------------------------------------------------------------
// Fused attention kernel: blocks [0,768) = MMA flash spatial (heads 0..5);
// blocks [768, 768+TEMP_BLKS) = temporal (heads 6..11), 416 thr each.
// ---------------------------------------------------------------------------
#define AT_T    416
#define MPAD    208
#define LDA     72
#define OQ      0
#define OK      (MPAD * LDA * 2)          // 29952
#define OV      (OK + 64 * LDA * 2)       // 39168
#define ATSMEM  (OV + 64 * LDA * 2)       // 48384

#define TEMP_TOT  (Bdim * 6 * Ndim)       // 150528
#define TEMP_BLKS ((TEMP_TOT + AT_T - 1) / AT_T)   // 362

__device__ __forceinline__ void spatial_body(char* smem)
{
    const uint32_t sb = smem_u32(smem);
    __half* Qs = (__half*)(smem + OQ);
    __half* Ks = (__half*)(smem + OK);
    __half* Vt = (__half*)(smem + OV);

    const int grp = blockIdx.x;
    const int b = grp / 96;
    const int h = (grp % 96) / 16;
    const int f = grp % 16;
    const size_t base = (((size_t)(b * Hh + h)) * Ndim + f * Pdim) * HD;

    const int tid  = threadIdx.x;
    const int lane = tid & 31;
    const int wid  = tid >> 5;
    const int gq   = lane >> 2;
    const int tg   = lane & 3;

    // fill Q
    {
        const uint4 z = make_uint4(0, 0, 0, 0);
        for (int idx = tid; idx < MPAD * 8; idx += AT_T) {
            int r = idx >> 3, c8 = (idx & 7) * 8;
            uint4 u = (r < Pdim) ? *(const uint4*)(g_q + base + (size_t)r * HD + c8) : z;
            *(uint4*)(Qs + r * LDA + c8) = u;
        }
    }
    __syncthreads();

    uint32_t qh[4][4];
    {
        const int arow = wid * 16 + (lane & 15);
        const int acol = (lane >> 4) * 8;
#pragma unroll
        for (int kb = 0; kb < 4; kb++) {
            uint32_t addr = sb + (uint32_t)((arow * LDA + kb * 16 + acol) * 2) + OQ;
            ldsm4(qh[kb][0], qh[kb][1], qh[kb][2], qh[kb][3], addr);
        }
    }

    float ofr[8][4];
#pragma unroll
    for (int j = 0; j < 8; j++)
#pragma unroll
        for (int q = 0; q < 4; q++) ofr[j][q] = 0.f;
    float mx0 = -1e30f, mx1 = -1e30f, ls0 = 0.f, ls1 = 0.f;
    const float scale = 0.125f;

    const int brow = ((lane >> 4) << 3) + (lane & 7);
    const int bcol = ((lane >> 3) & 1) * 8;

    for (int ch = 0; ch < 4; ch++) {
        __syncthreads();
        const int kbase = ch * 64;
        {
            const uint4 z = make_uint4(0, 0, 0, 0);
            for (int idx = tid; idx < 64 * 8; idx += AT_T) {
                int r = idx >> 3, c8 = (idx & 7) * 8;
                int key = kbase + r;
                uint4 u = (key < Pdim) ? *(const uint4*)(g_k + base + (size_t)key * HD + c8) : z;
                *(uint4*)(Ks + r * LDA + c8) = u;
            }
        }
        for (int idx = tid; idx < 64 * 8; idx += AT_T) {
            int r = idx >> 3, c8 = (idx & 7) * 8;
            int key = kbase + r;
            if (key < Pdim) {
                uint4 u = *(const uint4*)(g_v + base + (size_t)key * HD + c8);
                const __half* hp = (const __half*)&u;
#pragma unroll
                for (int j = 0; j < 8; j++) Vt[(c8 + j) * LDA + r] = hp[j];
            } else {
                const __half z = __float2half(0.f);
#pragma unroll
                for (int j = 0; j < 8; j++) Vt[(c8 + j) * LDA + r] = z;
            }
        }
        __syncthreads();

        float sfr[8][4];
#pragma unroll
        for (int j = 0; j < 8; j++)
#pragma unroll
            for (int q = 0; q < 4; q++) sfr[j][q] = 0.f;

#pragma unroll
        for (int kb = 0; kb < 4; kb++) {
#pragma unroll
            for (int p = 0; p < 4; p++) {
                uint32_t ka = sb + (uint32_t)(((p * 16 + brow) * LDA + kb * 16 + bcol) * 2) + OK;
                uint32_t bh0, bh1, bh2, bh3;
                ldsm4(bh0, bh1, bh2, bh3, ka);
                mma16816h(sfr[2 * p], qh[kb][0], qh[kb][1], qh[kb][2], qh[kb][3], bh0, bh1);
                mma16816h(sfr[2 * p + 1], qh[kb][0], qh[kb][1], qh[kb][2], qh[kb][3], bh2, bh3);
            }
        }

        const int nvalid = Pdim - kbase;
#pragma unroll
        for (int j = 0; j < 8; j++)
#pragma unroll
            for (int q = 0; q < 4; q++) {
                int key = j * 8 + 2 * tg + (q & 1);
                sfr[j][q] = (key < nvalid) ? sfr[j][q] * scale : -1e30f;
            }

        float rm0 = -1e30f, rm1 = -1e30f;
#pragma unroll
        for (int j = 0; j < 8; j++) {
            rm0 = fmaxf(rm0, fmaxf(sfr[j][0], sfr[j][1]));
            rm1 = fmaxf(rm1, fmaxf(sfr[j][2], sfr[j][3]));
        }
        rm0 = fmaxf(rm0, __shfl_xor_sync(0xFFFFFFFFu, rm0, 1));
        rm0 = fmaxf(rm0, __shfl_xor_sync(0xFFFFFFFFu, rm0, 2));
        rm1 = fmaxf(rm1, __shfl_xor_sync(0xFFFFFFFFu, rm1, 1));
        rm1 = fmaxf(rm1, __shfl_xor_sync(0xFFFFFFFFu, rm1, 2));
        float nm0 = fmaxf(mx0, rm0), nm1 = fmaxf(mx1, rm1);
        float c0 = __expf(mx0 - nm0), c1 = __expf(mx1 - nm1);
        mx0 = nm0; mx1 = nm1;
        ls0 *= c0; ls1 *= c1;
#pragma unroll
        for (int j = 0; j < 8; j++) {
            ofr[j][0] *= c0; ofr[j][1] *= c0;
            ofr[j][2] *= c1; ofr[j][3] *= c1;
        }

        float rs0 = 0.f, rs1 = 0.f;
#pragma unroll
        for (int j = 0; j < 8; j++) {
            float p0 = __expf(sfr[j][0] - nm0);
            float p1 = __expf(sfr[j][1] - nm0);
            float p2 = __expf(sfr[j][2] - nm1);
            float p3 = __expf(sfr[j][3] - nm1);
            rs0 += p0 + p1; rs1 += p2 + p3;
            sfr[j][0] = p0; sfr[j][1] = p1; sfr[j][2] = p2; sfr[j][3] = p3;
        }
        rs0 += __shfl_xor_sync(0xFFFFFFFFu, rs0, 1);
        rs0 += __shfl_xor_sync(0xFFFFFFFFu, rs0, 2);
        rs1 += __shfl_xor_sync(0xFFFFFFFFu, rs1, 1);
        rs1 += __shfl_xor_sync(0xFFFFFFFFu, rs1, 2);
        ls0 += rs0; ls1 += rs1;

#pragma unroll
        for (int kb = 0; kb < 4; kb++) {
            uint32_t pah[4], pal[4];
#pragma unroll
            for (int half = 0; half < 2; half++) {
                const int j = 2 * kb + half;
                float p0 = sfr[j][0], p1 = sfr[j][1], p2 = sfr[j][2], p3 = sfr[j][3];
                __half h0 = __float2half(p0);
                __half h1 = __float2half(p1);
                __half h2 = __float2half(p2);
                __half h3 = __float2half(p3);
                pah[2 * half + 0] = pack_h2(__half2float(h0), __half2float(h1));
                pah[2 * half + 1] = pack_h2(__half2float(h2), __half2float(h3));
                pal[2 * half + 0] = pack_h2(p0 - __half2float(h0), p1 - __half2float(h1));
                pal[2 * half + 1] = pack_h2(p2 - __half2float(h2), p3 - __half2float(h3));
            }
#pragma unroll
            for (int p = 0; p < 4; p++) {
                uint32_t va = sb + (uint32_t)(((p * 16 + brow) * LDA + kb * 16 + bcol) * 2) + OV;
                uint32_t vh0, vh1, vh2, vh3;
                ldsm4(vh0, vh1, vh2, vh3, va);
                mma16816h(ofr[2 * p], pah[0], pah[1], pah[2], pah[3], vh0, vh1);
                mma16816h(ofr[2 * p], pal[0], pal[1], pal[2], pal[3], vh0, vh1);
                mma16816h(ofr[2 * p + 1], pah[0], pah[1], pah[2], pah[3], vh2, vh3);
                mma16816h(ofr[2 * p + 1], pal[0], pal[1], pal[2], pal[3], vh2, vh3);
            }
        }
    }

    float inv0 = 1.f / ls0, inv1 = 1.f / ls1;
    const int r0 = wid * 16 + gq;
    const int r1 = r0 + 8;
    if (r0 < Pdim) {
        const size_t ob = ((size_t)b * Ndim + (f * Pdim + r0)) * Ddim + h * HD;
#pragma unroll
        for (int j = 0; j < 8; j++) {
            __half2 hv = __floats2half2_rn(ofr[j][0] * inv0, ofr[j][1] * inv0);
            *(__half2*)(g_wf + ob + j * 8 + 2 * tg) = hv;
        }
    }
    if (r1 < Pdim) {
        const size_t ob = ((size_t)b * Ndim + (f * Pdim + r1)) * Ddim + h * HD;
#pragma unroll
        for (int j = 0; j < 8; j++) {
            __half2 hv = __floats2half2_rn(ofr[j][2] * inv1, ofr[j][3] * inv1);
            *(__half2*)(g_wf + ob + j * 8 + 2 * tg) = hv;
        }
    }
}

__device__ __forceinline__ void temporal_body()
{
    int tid = (blockIdx.x - 768) * AT_T + threadIdx.x;
    if (tid >= TEMP_TOT) return;
    int b = tid / (6 * Ndim);
    int rr = tid - b * (6 * Ndim);
    int h = 6 + rr / Ndim;
    int n = rr % Ndim;
    int n0 = n & ~15;
    size_t row = (((size_t)(b * Hh + h)) * Ndim + n) * HD;
    size_t gb  = (((size_t)(b * Hh + h)) * Ndim + n0) * HD;

    float qr[64];
    {
        const uint4* qp = (const uint4*)(g_q + row);
#pragma unroll
        for (int i = 0; i < 8; i++) {
            uint4 u = qp[i];
            const __half2* hp = (const __half2*)&u;
#pragma unroll
            for (int j = 0; j < 4; j++) {
                float2 t = __half22float2(hp[j]);
                qr[i * 8 + 2 * j] = t.x;
                qr[i * 8 + 2 * j + 1] = t.y;
            }
        }
    }

    float s[16];
    float mx = -1e30f;
#pragma unroll
    for (int f = 0; f < 16; f++) {
        const uint4* kp = (const uint4*)(g_k + gb + (size_t)f * HD);
        float a = 0.f;
#pragma unroll
        for (int i = 0; i < 8; i++) {
            uint4 u = kp[i];
            const __half2* hp = (const __half2*)&u;
#pragma unroll
            for (int j = 0; j < 4; j++) {
                float2 t = __half22float2(hp[j]);
                a = fmaf(qr[i * 8 + 2 * j], t.x, a);
                a = fmaf(qr[i * 8 + 2 * j + 1], t.y, a);
            }
        }
        s[f] = a * 0.125f;
        mx = fmaxf(mx, s[f]);
    }
    float lsum = 0.f;
#pragma unroll
    for (int f = 0; f < 16; f++) { s[f] = __expf(s[f] - mx); lsum += s[f]; }
    float inv = 1.f / lsum;
#pragma unroll
    for (int f = 0; f < 16; f++) s[f] *= inv;

    const size_t obase = ((size_t)b * Ndim + n) * Ddim + h * HD;
#pragma unroll
    for (int ch = 0; ch < 4; ch++) {
        float a16[16];
#pragma unroll
        for (int i = 0; i < 16; i++) a16[i] = 0.f;
#pragma unroll
        for (int f = 0; f < 16; f++) {
            float p = s[f];
            const uint4* vp = (const uint4*)(g_v + gb + (size_t)f * HD + ch * 16);
#pragma unroll
            for (int i = 0; i < 2; i++) {
                uint4 u = vp[i];
                const __half2* hp = (const __half2*)&u;
#pragma unroll
                for (int j = 0; j < 4; j++) {
                    float2 t = __half22float2(hp[j]);
                    a16[i * 8 + 2 * j]     = fmaf(p, t.x, a16[i * 8 + 2 * j]);
                    a16[i * 8 + 2 * j + 1] = fmaf(p, t.y, a16[i * 8 + 2 * j + 1]);
                }
            }
        }
#pragma unroll
        for (int i = 0; i < 8; i++) {
            __half2 hv = __floats2half2_rn(a16[2 * i], a16[2 * i + 1]);
            *(__half2*)(g_wf + obase + ch * 16 + 2 * i) = hv;
        }
    }
}

__global__ __launch_bounds__(AT_T, 1) void attn_fused_k()
{
    extern __shared__ char smem[];
    if (blockIdx.x < 768) spatial_body(smem);
    else                  temporal_body();
}

// ---------------------------------------------------------------------------
// Launch
// ---------------------------------------------------------------------------
extern "C" void kernel_launch(void* const* d_in, const int* in_sizes, int n_in,
                              void* d_out, int out_size)
{
    const float* x      = (const float*)d_in[0];
    const float* w_qkv  = (const float*)d_in[1];
    const float* w_proj = (const float*)d_in[2];
    const float* b_proj = (const float*)d_in[3];
    float* out = (float*)d_out;

    __half *p_q, *p_k, *p_v, *p_x, *p_wqkv, *p_wproj, *p_wf;
    cudaGetSymbolAddress((void**)&p_q, g_q);
    cudaGetSymbolAddress((void**)&p_k, g_k);
    cudaGetSymbolAddress((void**)&p_v, g_v);
    cudaGetSymbolAddress((void**)&p_x, g_x);
    cudaGetSymbolAddress((void**)&p_wqkv, g_wqkv);
    cudaGetSymbolAddress((void**)&p_wproj, g_wproj);
    cudaGetSymbolAddress((void**)&p_wf, g_wf);

    cudaFuncSetAttribute(tgemm_k, cudaFuncAttributeMaxDynamicSharedMemorySize, GSMEM);
    cudaFuncSetAttribute(attn_fused_k, cudaFuncAttributeMaxDynamicSharedMemorySize, ATSMEM);

    // 0) fused fp16 conversions (one launch)
    const size_t CVT_TOT = MD_ELEMS + WQKV_ELEMS + WPRJ_ELEMS;
    cvt_all_k<<<(unsigned)((CVT_TOT + 255) / 256), 256>>>(x, w_qkv, w_proj);

    // 1) qkv GEMM (1-pass, 2-stage) with fused scatter into fp16 q/k/v
    tgemm_k<<<dim3(E3 / 128, Mrows / 128), 256, GSMEM>>>(
        p_x, p_wqkv, nullptr, nullptr, E3, 0, p_q, p_k, p_v);

    // 2) fused spatial + temporal attention
    attn_fused_k<<<768 + TEMP_BLKS, AT_T, ATSMEM>>>();

    // 3) out = wf @ w_proj^T + b_proj (1-pass, 2-stage)
    tgemm_k<<<dim3(Ddim / 128, Mrows / 128), 256, GSMEM>>>(
        p_wf, p_wproj, b_proj, out, Ddim, 1, nullptr, nullptr, nullptr);
}